// round 3
// baseline (speedup 1.0000x reference)
#include <cuda_runtime.h>
#include <math.h>

#define NBATCH 8
#define T0C    8192
#define INCH   256
#define HIDC   128
#define MIDC   512
#define OUTC   256
#define NL     20
#define TGT    6146
#define RST    8192

// ---------------- device scratch (allowed: __device__ globals) ----------------
__device__ float g_res0[(size_t)NBATCH * HIDC * RST];          // 33.5 MB
__device__ float g_res1[(size_t)NBATCH * HIDC * RST];          // 33.5 MB
__device__ float g_final[(size_t)NBATCH * HIDC * TGT];         // 25 MB
__device__ float g_WA[(size_t)NL * 256 * 256];                 // packed [l][k][row], rows: 0..127=f, 128..255=g
__device__ float g_WR[(size_t)NL * HIDC * HIDC];               // packed [l][k][o]
__device__ float g_WiP[INCH * HIDC];                           // [k][o]
__device__ float g_W1P[HIDC * MIDC];                           // [k][o]
__device__ float g_W2P[MIDC * OUTC];                           // [k][o]

// ---------------- weight packing ----------------
__global__ void pack_fg(const float* __restrict__ Wf, const float* __restrict__ Wg) {
    int i = blockIdx.x * 256 + threadIdx.x;          // NL*256*256
    if (i >= NL * 256 * 256) return;
    int row = i & 255;
    int k   = (i >> 8) & 255;
    int l   = i >> 16;
    const float* W = (row < 128) ? Wf : Wg;
    int o = row & 127;
    g_WA[i] = W[(((size_t)l * 128 + o) * 128 + (k & 127)) * 2 + (k >> 7)];
}

__global__ void pack_r(const float* __restrict__ Wr) {
    int i = blockIdx.x * 256 + threadIdx.x;          // NL*128*128
    if (i >= NL * 128 * 128) return;
    int o = i & 127;
    int k = (i >> 7) & 127;
    int l = i >> 14;
    g_WR[i] = Wr[((size_t)l * 128 + o) * 128 + k];
}

__global__ void pack_t(float* __restrict__ dst, const float* __restrict__ src, int O, int K) {
    int i = blockIdx.x * 256 + threadIdx.x;          // O*K, dst[k*O+o] = src[o*K+k]
    if (i >= O * K) return;
    int o = i % O;
    int k = i / O;
    dst[i] = src[o * K + k];
}

// ---------------- input 1x1 conv: res0 = Wi @ inputs + bi ----------------
__global__ __launch_bounds__(256, 2)
void input_conv_k(const float* __restrict__ inp, const float* __restrict__ bi) {
    extern __shared__ float sm[];
    float (*sX)[64]  = (float(*)[64])sm;                 // 256 x 64
    float (*sW)[128] = (float(*)[128])(sm + 256 * 64);   // 16 x 128

    int b   = blockIdx.y;
    int t0  = blockIdx.x * 64;
    int tid = threadIdx.x;
    const float* src = inp + (size_t)b * INCH * T0C;

    #pragma unroll 4
    for (int j = 0; j < 64; j++) {
        int idx = j * 256 + tid;
        int row = idx >> 6, col = idx & 63;
        sX[row][col] = src[(size_t)row * T0C + t0 + col];
    }

    int rb = tid >> 3, cb = tid & 7;
    int rb4 = rb * 4, cb8 = cb * 8;
    float acc[4][8];
    #pragma unroll
    for (int u = 0; u < 4; u++)
        #pragma unroll
        for (int v = 0; v < 8; v++) acc[u][v] = 0.f;

    for (int k0 = 0; k0 < 256; k0 += 16) {
        __syncthreads();
        #pragma unroll
        for (int j = 0; j < 8; j++) {
            int idx = j * 256 + tid;
            int kc = idx >> 7, r = idx & 127;
            sW[kc][r] = g_WiP[(size_t)(k0 + kc) * 128 + r];
        }
        __syncthreads();
        #pragma unroll
        for (int kc = 0; kc < 16; kc++) {
            float4 w  = *(const float4*)&sW[kc][rb4];
            float4 x0 = *(const float4*)&sX[k0 + kc][cb8];
            float4 x1 = *(const float4*)&sX[k0 + kc][cb8 + 4];
            float wv[4] = {w.x, w.y, w.z, w.w};
            float xv[8] = {x0.x, x0.y, x0.z, x0.w, x1.x, x1.y, x1.z, x1.w};
            #pragma unroll
            for (int u = 0; u < 4; u++)
                #pragma unroll
                for (int v = 0; v < 8; v++)
                    acc[u][v] = fmaf(wv[u], xv[v], acc[u][v]);
        }
    }
    __syncthreads();
    #pragma unroll
    for (int u = 0; u < 4; u++) {
        float bo = bi[rb4 + u];
        #pragma unroll
        for (int v = 0; v < 8; v++)
            sX[rb4 + u][cb8 + v] = acc[u][v] + bo;
    }
    __syncthreads();
    float* dst = g_res0 + (size_t)b * HIDC * RST;
    #pragma unroll 4
    for (int j = 0; j < 32; j++) {
        int idx = j * 256 + tid;
        int row = idx >> 6, col = idx & 63;
        dst[(size_t)row * RST + t0 + col] = sX[row][col];
    }
}

// ---------------- fused residual layer ----------------
__global__ __launch_bounds__(256, 2)
void layer_k(const float* __restrict__ rin, float* __restrict__ rout,
             const float* __restrict__ bf, const float* __restrict__ bg,
             const float* __restrict__ br,
             int l, int d, int Tin, int Tout, int first) {
    extern __shared__ float sm[];
    float (*sX)[64]  = (float(*)[64])sm;                 // 256 x 64 (rows 0..127 reused)
    float (*sW)[256] = (float(*)[256])(sm + 256 * 64);   // 16 x 256

    int b   = blockIdx.y;
    int t0  = blockIdx.x * 64;
    int tid = threadIdx.x;
    const float* src = rin + (size_t)b * HIDC * RST;

    // load X: rows 0..127 = res[:,t], rows 128..255 = res[:,t+d]
    #pragma unroll 4
    for (int j = 0; j < 64; j++) {
        int idx = j * 256 + tid;
        int row = idx >> 6, col = idx & 63;
        int t = t0 + col + ((row >= 128) ? d : 0);
        int ch = row & 127;
        sX[row][col] = (t < Tin) ? src[(size_t)ch * RST + t] : 0.f;
    }

    int rb = tid >> 3, cb = tid & 7;
    int rb4 = rb * 4, cb8 = cb * 8;
    float fa[4][8], ga[4][8];
    #pragma unroll
    for (int u = 0; u < 4; u++)
        #pragma unroll
        for (int v = 0; v < 8; v++) { fa[u][v] = 0.f; ga[u][v] = 0.f; }

    const float* WAl = g_WA + (size_t)l * 256 * 256;
    for (int k0 = 0; k0 < 256; k0 += 16) {
        __syncthreads();
        #pragma unroll
        for (int j = 0; j < 16; j++)
            sW[j][tid] = WAl[(size_t)(k0 + j) * 256 + tid];
        __syncthreads();
        #pragma unroll
        for (int kc = 0; kc < 16; kc++) {
            float4 wf = *(const float4*)&sW[kc][rb4];
            float4 wg = *(const float4*)&sW[kc][128 + rb4];
            float4 x0 = *(const float4*)&sX[k0 + kc][cb8];
            float4 x1 = *(const float4*)&sX[k0 + kc][cb8 + 4];
            float wfv[4] = {wf.x, wf.y, wf.z, wf.w};
            float wgv[4] = {wg.x, wg.y, wg.z, wg.w};
            float xv[8]  = {x0.x, x0.y, x0.z, x0.w, x1.x, x1.y, x1.z, x1.w};
            #pragma unroll
            for (int u = 0; u < 4; u++)
                #pragma unroll
                for (int v = 0; v < 8; v++) {
                    fa[u][v] = fmaf(wfv[u], xv[v], fa[u][v]);
                    ga[u][v] = fmaf(wgv[u], xv[v], ga[u][v]);
                }
        }
    }
    __syncthreads();

    // activations: out = tanh(f) * sigmoid(g)  -> into sX rows 0..127
    const float* bfl = bf + l * 128;
    const float* bgl = bg + l * 128;
    #pragma unroll
    for (int u = 0; u < 4; u++) {
        int o = rb4 + u;
        float bfo = bfl[o], bgo = bgl[o];
        #pragma unroll
        for (int v = 0; v < 8; v++) {
            float f = tanhf(fa[u][v] + bfo);
            float g = 1.f / (1.f + expf(-(ga[u][v] + bgo)));
            sX[o][cb8 + v] = f * g;
        }
    }
    __syncthreads();

    // GEMM2: x = Wr @ out
    float acc[4][8];
    #pragma unroll
    for (int u = 0; u < 4; u++)
        #pragma unroll
        for (int v = 0; v < 8; v++) acc[u][v] = 0.f;

    const float* WRl = g_WR + (size_t)l * 128 * 128;
    for (int k0 = 0; k0 < 128; k0 += 16) {
        __syncthreads();
        #pragma unroll
        for (int j = 0; j < 8; j++) {
            int idx = j * 256 + tid;
            int kc = idx >> 7, r = idx & 127;
            sW[kc][r] = WRl[(size_t)(k0 + kc) * 128 + r];
        }
        __syncthreads();
        #pragma unroll
        for (int kc = 0; kc < 16; kc++) {
            float4 w  = *(const float4*)&sW[kc][rb4];
            float4 x0 = *(const float4*)&sX[k0 + kc][cb8];
            float4 x1 = *(const float4*)&sX[k0 + kc][cb8 + 4];
            float wv[4] = {w.x, w.y, w.z, w.w};
            float xv[8] = {x0.x, x0.y, x0.z, x0.w, x1.x, x1.y, x1.z, x1.w};
            #pragma unroll
            for (int u = 0; u < 4; u++)
                #pragma unroll
                for (int v = 0; v < 8; v++)
                    acc[u][v] = fmaf(wv[u], xv[v], acc[u][v]);
        }
    }
    __syncthreads();

    // stage x into sX rows 0..127 for coalesced epilogue
    const float* brl = br + l * 128;
    #pragma unroll
    for (int u = 0; u < 4; u++) {
        float bo = brl[rb4 + u];
        #pragma unroll
        for (int v = 0; v < 8; v++)
            sX[rb4 + u][cb8 + v] = acc[u][v] + bo;
    }
    __syncthreads();

    float* dst = rout + (size_t)b * HIDC * RST;
    float* fin = g_final + (size_t)b * HIDC * TGT;
    int off = Tout - TGT;
    #pragma unroll 4
    for (int j = 0; j < 32; j++) {
        int idx = j * 256 + tid;
        int row = idx >> 6, col = idx & 63;
        int t = t0 + col;
        if (t < Tout) {
            float xv = sX[row][col];
            dst[(size_t)row * RST + t] = xv + sX[128 + row][col];  // residual: x + res[:,t+d]
            int tf = t - off;
            if (tf >= 0) {
                float* p = &fin[(size_t)row * TGT + tf];
                *p = first ? xv : (*p + xv);
            }
        }
    }
}

// ---------------- head: relu -> W1 -> relu -> W2 -> transpose out ----------------
__global__ __launch_bounds__(256, 2)
void head_k(const float* __restrict__ b1, const float* __restrict__ b2,
            float* __restrict__ out) {
    extern __shared__ float sm[];
    float (*sF)[32] = (float(*)[32])sm;                       // 128 x 32
    float (*sH)[32] = (float(*)[32])(sm + 128 * 32);          // 512 x 32
    float* sWf = sm + 128 * 32 + 512 * 32;                    // 16 x 512 flat

    int b   = blockIdx.y;
    int t0  = blockIdx.x * 32;
    int tid = threadIdx.x;
    const float* fin = g_final + (size_t)b * HIDC * TGT;

    #pragma unroll
    for (int j = 0; j < 16; j++) {
        int idx = j * 256 + tid;
        int row = idx >> 5, col = idx & 31;
        int t = t0 + col;
        sF[row][col] = (t < TGT) ? fmaxf(fin[(size_t)row * TGT + t], 0.f) : 0.f;
    }

    // GEMM h1: 512 x 32, k=128
    int rb = tid >> 2, cb = tid & 3;      // rb 0..63 -> rows rb*8, cb 0..3 -> cols cb*8
    int rb8 = rb * 8, cb8 = cb * 8;
    float a1[8][8];
    #pragma unroll
    for (int u = 0; u < 8; u++)
        #pragma unroll
        for (int v = 0; v < 8; v++) a1[u][v] = 0.f;

    for (int k0 = 0; k0 < 128; k0 += 16) {
        __syncthreads();
        #pragma unroll
        for (int j = 0; j < 32; j++) {
            int idx = j * 256 + tid;
            int kc = idx >> 9, r = idx & 511;
            sWf[kc * 512 + r] = g_W1P[(size_t)(k0 + kc) * 512 + r];
        }
        __syncthreads();
        #pragma unroll
        for (int kc = 0; kc < 16; kc++) {
            float4 w0 = *(const float4*)&sWf[kc * 512 + rb8];
            float4 w1 = *(const float4*)&sWf[kc * 512 + rb8 + 4];
            float4 x0 = *(const float4*)&sF[k0 + kc][cb8];
            float4 x1 = *(const float4*)&sF[k0 + kc][cb8 + 4];
            float wv[8] = {w0.x, w0.y, w0.z, w0.w, w1.x, w1.y, w1.z, w1.w};
            float xv[8] = {x0.x, x0.y, x0.z, x0.w, x1.x, x1.y, x1.z, x1.w};
            #pragma unroll
            for (int u = 0; u < 8; u++)
                #pragma unroll
                for (int v = 0; v < 8; v++)
                    a1[u][v] = fmaf(wv[u], xv[v], a1[u][v]);
        }
    }
    __syncthreads();
    #pragma unroll
    for (int u = 0; u < 8; u++) {
        float bo = b1[rb8 + u];
        #pragma unroll
        for (int v = 0; v < 8; v++)
            sH[rb8 + u][cb8 + v] = fmaxf(a1[u][v] + bo, 0.f);
    }
    __syncthreads();

    // GEMM out: 256 x 32, k=512 ; lane-major mapping for coalesced stores
    int lane = tid & 31, wp = tid >> 5;   // o = lane + 32u (u<8), c = wp*4 + v (v<4)
    float a2[8][4];
    #pragma unroll
    for (int u = 0; u < 8; u++)
        #pragma unroll
        for (int v = 0; v < 4; v++) a2[u][v] = 0.f;

    for (int k0 = 0; k0 < 512; k0 += 16) {
        __syncthreads();
        #pragma unroll
        for (int j = 0; j < 16; j++) {
            int idx = j * 256 + tid;
            int kc = idx >> 8, r = idx & 255;
            sWf[kc * 256 + r] = g_W2P[(size_t)(k0 + kc) * 256 + r];
        }
        __syncthreads();
        #pragma unroll
        for (int kc = 0; kc < 16; kc++) {
            float xv[4];
            #pragma unroll
            for (int v = 0; v < 4; v++) xv[v] = sH[k0 + kc][wp * 4 + v];
            #pragma unroll
            for (int u = 0; u < 8; u++) {
                float w = sWf[kc * 256 + lane + 32 * u];
                #pragma unroll
                for (int v = 0; v < 4; v++)
                    a2[u][v] = fmaf(w, xv[v], a2[u][v]);
            }
        }
    }

    float bias[8];
    #pragma unroll
    for (int u = 0; u < 8; u++) bias[u] = b2[lane + 32 * u];

    #pragma unroll
    for (int v = 0; v < 4; v++) {
        int t = t0 + wp * 4 + v;
        if (t < TGT) {
            float* dp = out + ((size_t)b * TGT + t) * 256;
            #pragma unroll
            for (int u = 0; u < 8; u++)
                dp[lane + 32 * u] = a2[u][v] + bias[u];
        }
    }
}

// ---------------- launch ----------------
static const int DIL[NL] = {1, 2, 4, 8, 16, 32, 64, 128, 256, 512,
                            1, 2, 4, 8, 16, 32, 64, 128, 256, 512};

extern "C" void kernel_launch(void* const* d_in, const int* in_sizes, int n_in,
                              void* d_out, int out_size) {
    const float* inputs = (const float*)d_in[0];
    const float* Wi = (const float*)d_in[1];
    const float* bi = (const float*)d_in[2];
    const float* Wf = (const float*)d_in[3];
    const float* bf = (const float*)d_in[4];
    const float* Wg = (const float*)d_in[5];
    const float* bg = (const float*)d_in[6];
    const float* Wr = (const float*)d_in[7];
    const float* br = (const float*)d_in[8];
    const float* W1 = (const float*)d_in[9];
    const float* b1 = (const float*)d_in[10];
    const float* W2 = (const float*)d_in[11];
    const float* b2 = (const float*)d_in[12];
    float* out = (float*)d_out;

    float *p_res0, *p_res1, *p_wip, *p_w1p, *p_w2p;
    cudaGetSymbolAddress((void**)&p_res0, g_res0);
    cudaGetSymbolAddress((void**)&p_res1, g_res1);
    cudaGetSymbolAddress((void**)&p_wip, g_WiP);
    cudaGetSymbolAddress((void**)&p_w1p, g_W1P);
    cudaGetSymbolAddress((void**)&p_w2p, g_W2P);

    cudaFuncSetAttribute(input_conv_k, cudaFuncAttributeMaxDynamicSharedMemorySize, 73728);
    cudaFuncSetAttribute(layer_k,      cudaFuncAttributeMaxDynamicSharedMemorySize, 81920);
    cudaFuncSetAttribute(head_k,       cudaFuncAttributeMaxDynamicSharedMemorySize, 114688);

    pack_fg<<<NL * 256 * 256 / 256, 256>>>(Wf, Wg);
    pack_r<<<NL * 128 * 128 / 256, 256>>>(Wr);
    pack_t<<<(INCH * HIDC) / 256, 256>>>(p_wip, Wi, HIDC, INCH);
    pack_t<<<(HIDC * MIDC) / 256, 256>>>(p_w1p, W1, MIDC, HIDC);
    pack_t<<<(MIDC * OUTC) / 256, 256>>>(p_w2p, W2, OUTC, MIDC);

    input_conv_k<<<dim3(T0C / 64, NBATCH), 256, 73728>>>(inputs, bi);

    int Tin = T0C;
    float* rin = p_res0;
    float* rout = p_res1;
    for (int l = 0; l < NL; l++) {
        int d = DIL[l];
        int Tout = Tin - d;
        dim3 grid((Tout + 63) / 64, NBATCH);
        layer_k<<<grid, 256, 81920>>>(rin, rout, bf, bg, br, l, d, Tin, Tout, l == 0 ? 1 : 0);
        float* tmp = rin; rin = rout; rout = tmp;
        Tin = Tout;
    }

    head_k<<<dim3((TGT + 31) / 32, NBATCH), 256, 114688>>>(b1, b2, out);
}

// round 6
// speedup vs baseline: 1.2090x; 1.2090x over previous
#include <cuda_runtime.h>
#include <mma.h>
#include <math.h>

using namespace nvcuda;

#define NBATCH 8
#define T0C    8192
#define INCH   256
#define HIDC   128
#define MIDC   512
#define OUTC   256
#define NL     20
#define TGT    6146
#define RST    8192

#define XLD    68     // 256-row X tile, padded ld (68*4 bytes, 16B-divisible)
#define WLD1   264    // GEMM1 A chunk ld (M=256)
#define WLD2   136    // GEMM2 A chunk ld (M=128)
#define WLDI   136    // input conv A chunk ld (M=128)
#define HLD    36     // head tile ld (N=32)
#define W1LD   520    // head GEMM1 A ld (M=512)
#define W2LD   264    // head GEMM2 A ld (M=256)

typedef wmma::fragment<wmma::matrix_a, 16, 16, 8, wmma::precision::tf32, wmma::col_major> FragA;
typedef wmma::fragment<wmma::matrix_b, 16, 16, 8, wmma::precision::tf32, wmma::row_major> FragB;
typedef wmma::fragment<wmma::accumulator, 16, 16, 8, float> FragC;

// ---------------- device scratch ----------------
__device__ float g_res0[(size_t)NBATCH * HIDC * RST];
__device__ float g_res1[(size_t)NBATCH * HIDC * RST];
__device__ float g_final[(size_t)NBATCH * HIDC * TGT];
__device__ float g_WA[(size_t)NL * 256 * 256];   // tf32 [l][k][row], rows 0..127=f, 128..255=g
__device__ float g_WR[(size_t)NL * HIDC * HIDC]; // tf32 [l][k][o]
__device__ float g_WiP[INCH * HIDC];             // tf32 [k][o]
__device__ float g_W1P[HIDC * MIDC];             // tf32 [k][o]
__device__ float g_W2P[MIDC * OUTC];             // tf32 [k][o]

// ---------------- weight packing (convert to tf32 once) ----------------
__global__ void pack_fg(const float* __restrict__ Wf, const float* __restrict__ Wg) {
    int i = blockIdx.x * 256 + threadIdx.x;
    if (i >= NL * 256 * 256) return;
    int row = i & 255;
    int k   = (i >> 8) & 255;
    int l   = i >> 16;
    const float* W = (row < 128) ? Wf : Wg;
    int o = row & 127;
    g_WA[i] = wmma::__float_to_tf32(W[(((size_t)l * 128 + o) * 128 + (k & 127)) * 2 + (k >> 7)]);
}

__global__ void pack_r(const float* __restrict__ Wr) {
    int i = blockIdx.x * 256 + threadIdx.x;
    if (i >= NL * 128 * 128) return;
    int o = i & 127;
    int k = (i >> 7) & 127;
    int l = i >> 14;
    g_WR[i] = wmma::__float_to_tf32(Wr[((size_t)l * 128 + o) * 128 + k]);
}

__global__ void pack_t(float* __restrict__ dst, const float* __restrict__ src, int O, int K) {
    int i = blockIdx.x * 256 + threadIdx.x;
    if (i >= O * K) return;
    int o = i % O;
    int k = i / O;
    dst[i] = wmma::__float_to_tf32(src[o * K + k]);
}

// ---------------- input 1x1 conv (tf32 WMMA): res0 = Wi @ inputs + bi ----------------
__global__ __launch_bounds__(256)
void input_conv_k(const float* __restrict__ inp, const float* __restrict__ bi) {
    extern __shared__ float sm[];
    float* sX = sm;                    // 256 x XLD
    float* sW = sm + 256 * XLD;        // 16 x WLDI

    int b   = blockIdx.y;
    int t0  = blockIdx.x * 64;
    int tid = threadIdx.x;
    int wid = tid >> 5;
    const float* src = inp + (size_t)b * INCH * T0C;

    #pragma unroll 4
    for (int j = 0; j < 64; j++) {
        int idx = j * 256 + tid;
        int row = idx >> 6, col = idx & 63;
        sX[row * XLD + col] = wmma::__float_to_tf32(src[(size_t)row * T0C + t0 + col]);
    }

    int wM = wid >> 1, wN = wid & 1;
    int m0 = wM * 32, n0 = wN * 32;
    FragC acc[2][2];
    #pragma unroll
    for (int i = 0; i < 2; i++)
        #pragma unroll
        for (int j = 0; j < 2; j++) wmma::fill_fragment(acc[i][j], 0.f);

    for (int k0 = 0; k0 < 256; k0 += 16) {
        __syncthreads();
        #pragma unroll
        for (int j = 0; j < 8; j++) {
            int idx = j * 256 + tid;
            int kc = idx >> 7, r = idx & 127;
            sW[kc * WLDI + r] = g_WiP[(size_t)(k0 + kc) * 128 + r];
        }
        __syncthreads();
        #pragma unroll
        for (int ks = 0; ks < 2; ks++) {
            FragA a[2]; FragB bb[2];
            #pragma unroll
            for (int i = 0; i < 2; i++)
                wmma::load_matrix_sync(a[i], sW + ks * 8 * WLDI + m0 + i * 16, WLDI);
            #pragma unroll
            for (int j = 0; j < 2; j++)
                wmma::load_matrix_sync(bb[j], sX + (k0 + ks * 8) * XLD + n0 + j * 16, XLD);
            #pragma unroll
            for (int i = 0; i < 2; i++)
                #pragma unroll
                for (int j = 0; j < 2; j++)
                    wmma::mma_sync(acc[i][j], a[i], bb[j], acc[i][j]);
        }
    }
    __syncthreads();
    #pragma unroll
    for (int i = 0; i < 2; i++)
        #pragma unroll
        for (int j = 0; j < 2; j++)
            wmma::store_matrix_sync(sX + (m0 + i * 16) * XLD + n0 + j * 16, acc[i][j], XLD, wmma::mem_row_major);
    __syncthreads();

    float* dst = g_res0 + (size_t)b * HIDC * RST;
    #pragma unroll 4
    for (int j = 0; j < 32; j++) {
        int idx = j * 256 + tid;
        int row = idx >> 6, col = idx & 63;
        dst[(size_t)row * RST + t0 + col] = sX[row * XLD + col] + bi[row];
    }
}

// ---------------- fused residual layer (tf32 WMMA) ----------------
__global__ __launch_bounds__(256)
void layer_k(const float* __restrict__ rin, float* __restrict__ rout,
             const float* __restrict__ bf, const float* __restrict__ bg,
             const float* __restrict__ br,
             int l, int d, int Tin, int Tout, int first) {
    extern __shared__ float sm[];
    float* sX = sm;                    // 256 x XLD
    float* sW = sm + 256 * XLD;        // 16 x WLD1

    int b   = blockIdx.y;
    int t0  = blockIdx.x * 64;
    int tid = threadIdx.x;
    int wid = tid >> 5;
    const float* src = rin + (size_t)b * HIDC * RST;

    // stage X (tf32): rows 0..127 = res[:,t], rows 128..255 = res[:,t+d]
    #pragma unroll 4
    for (int j = 0; j < 64; j++) {
        int idx = j * 256 + tid;
        int row = idx >> 6, col = idx & 63;
        int t = t0 + col + ((row >= 128) ? d : 0);
        int ch = row & 127;
        float v = (t < Tin) ? src[(size_t)ch * RST + t] : 0.f;
        sX[row * XLD + col] = wmma::__float_to_tf32(v);
    }

    // ---- GEMM1: [256 x 256] @ [256 x 64] ----
    int wM = wid >> 1, wN = wid & 1;
    int m0 = wM * 64, n0 = wN * 32;
    FragC acc1[4][2];
    #pragma unroll
    for (int i = 0; i < 4; i++)
        #pragma unroll
        for (int j = 0; j < 2; j++) wmma::fill_fragment(acc1[i][j], 0.f);

    const float* WAl = g_WA + (size_t)l * 256 * 256;
    for (int k0 = 0; k0 < 256; k0 += 16) {
        __syncthreads();
        #pragma unroll
        for (int j = 0; j < 16; j++) {
            int idx = j * 256 + tid;
            int kc = idx >> 8, r = idx & 255;
            sW[kc * WLD1 + r] = WAl[(size_t)(k0 + kc) * 256 + r];
        }
        __syncthreads();
        #pragma unroll
        for (int ks = 0; ks < 2; ks++) {
            FragA a[4]; FragB bb[2];
            #pragma unroll
            for (int i = 0; i < 4; i++)
                wmma::load_matrix_sync(a[i], sW + ks * 8 * WLD1 + m0 + i * 16, WLD1);
            #pragma unroll
            for (int j = 0; j < 2; j++)
                wmma::load_matrix_sync(bb[j], sX + (k0 + ks * 8) * XLD + n0 + j * 16, XLD);
            #pragma unroll
            for (int i = 0; i < 4; i++)
                #pragma unroll
                for (int j = 0; j < 2; j++)
                    wmma::mma_sync(acc1[i][j], a[i], bb[j], acc1[i][j]);
        }
    }
    __syncthreads();   // all warps done reading sX before overwrite
    #pragma unroll
    for (int i = 0; i < 4; i++)
        #pragma unroll
        for (int j = 0; j < 2; j++)
            wmma::store_matrix_sync(sX + (m0 + i * 16) * XLD + n0 + j * 16, acc1[i][j], XLD, wmma::mem_row_major);
    __syncthreads();

    // ---- activation: act = tanh(f+bf) * sigmoid(g+bg), tf32, in place (rows 0..127) ----
    const float* bfl = bf + l * 128;
    const float* bgl = bg + l * 128;
    #pragma unroll
    for (int j = 0; j < 32; j++) {
        int idx = j * 256 + tid;
        int o = idx >> 6, t = idx & 63;
        float f = tanhf(sX[o * XLD + t] + bfl[o]);
        float g = 1.f / (1.f + expf(-(sX[(128 + o) * XLD + t] + bgl[o])));
        sX[o * XLD + t] = wmma::__float_to_tf32(f * g);
    }
    __syncthreads();

    // ---- GEMM2: [128 x 128] @ [128 x 64] ----
    int m2 = wM * 32, n2 = wN * 32;
    FragC acc2[2][2];
    #pragma unroll
    for (int i = 0; i < 2; i++)
        #pragma unroll
        for (int j = 0; j < 2; j++) wmma::fill_fragment(acc2[i][j], 0.f);

    const float* WRl = g_WR + (size_t)l * 128 * 128;
    for (int k0 = 0; k0 < 128; k0 += 16) {
        __syncthreads();
        #pragma unroll
        for (int j = 0; j < 8; j++) {
            int idx = j * 256 + tid;
            int kc = idx >> 7, r = idx & 127;
            sW[kc * WLD2 + r] = WRl[(size_t)(k0 + kc) * 128 + r];
        }
        __syncthreads();
        #pragma unroll
        for (int ks = 0; ks < 2; ks++) {
            FragA a[2]; FragB bb[2];
            #pragma unroll
            for (int i = 0; i < 2; i++)
                wmma::load_matrix_sync(a[i], sW + ks * 8 * WLD2 + m2 + i * 16, WLD2);
            #pragma unroll
            for (int j = 0; j < 2; j++)
                wmma::load_matrix_sync(bb[j], sX + (k0 + ks * 8) * XLD + n2 + j * 16, XLD);
            #pragma unroll
            for (int i = 0; i < 2; i++)
                #pragma unroll
                for (int j = 0; j < 2; j++)
                    wmma::mma_sync(acc2[i][j], a[i], bb[j], acc2[i][j]);
        }
    }
    __syncthreads();
    // stage x into sX rows 128..255 (free: g consumed)
    #pragma unroll
    for (int i = 0; i < 2; i++)
        #pragma unroll
        for (int j = 0; j < 2; j++)
            wmma::store_matrix_sync(sX + (128 + m2 + i * 16) * XLD + n2 + j * 16, acc2[i][j], XLD, wmma::mem_row_major);
    __syncthreads();

    // ---- epilogue (full fp32; residual operand re-read from global, L2 hit) ----
    const float* brl = br + l * 128;
    float* dst = rout + (size_t)b * HIDC * RST;
    float* fin = g_final + (size_t)b * HIDC * TGT;
    int off = Tout - TGT;
    #pragma unroll 4
    for (int j = 0; j < 32; j++) {
        int idx = j * 256 + tid;
        int row = idx >> 6, col = idx & 63;
        int t = t0 + col;
        if (t < Tout) {
            float xv = sX[(128 + row) * XLD + col] + brl[row];
            dst[(size_t)row * RST + t] = xv + src[(size_t)row * RST + t + d];
            int tf = t - off;
            if (tf >= 0) {
                float* p = &fin[(size_t)row * TGT + tf];
                *p = first ? xv : (*p + xv);
            }
        }
    }
}

// ---------------- head (tf32 WMMA): relu -> W1 -> relu -> W2 -> transpose ----------------
__global__ __launch_bounds__(256)
void head_k(const float* __restrict__ b1, const float* __restrict__ b2,
            float* __restrict__ out) {
    extern __shared__ float sm[];
    float* sF = sm;                             // 128 x HLD
    float* sH = sm + 128 * HLD;                 // 512 x HLD
    float* sW = sm + 128 * HLD + 512 * HLD;     // max(16*W1LD, 256*32) = 9216 floats

    int b   = blockIdx.y;
    int t0  = blockIdx.x * 32;
    int tid = threadIdx.x;
    int wid = tid >> 5;
    const float* fin = g_final + (size_t)b * HIDC * TGT;

    #pragma unroll
    for (int j = 0; j < 16; j++) {
        int idx = j * 256 + tid;
        int row = idx >> 5, col = idx & 31;
        int t = t0 + col;
        float v = (t < TGT) ? fmaxf(fin[(size_t)row * TGT + t], 0.f) : 0.f;
        sF[row * HLD + col] = wmma::__float_to_tf32(v);
    }

    // ---- GEMM h1: [512 x 128] @ [128 x 32]; warp wid owns rows wid*64..+63 ----
    FragC a1[4][2];
    #pragma unroll
    for (int i = 0; i < 4; i++)
        #pragma unroll
        for (int j = 0; j < 2; j++) wmma::fill_fragment(a1[i][j], 0.f);

    for (int k0 = 0; k0 < 128; k0 += 16) {
        __syncthreads();
        #pragma unroll
        for (int j = 0; j < 32; j++) {
            int idx = j * 256 + tid;
            int kc = idx >> 9, r = idx & 511;
            sW[kc * W1LD + r] = g_W1P[(size_t)(k0 + kc) * 512 + r];
        }
        __syncthreads();
        #pragma unroll
        for (int ks = 0; ks < 2; ks++) {
            FragA a[4]; FragB bb[2];
            #pragma unroll
            for (int i = 0; i < 4; i++)
                wmma::load_matrix_sync(a[i], sW + ks * 8 * W1LD + wid * 64 + i * 16, W1LD);
            #pragma unroll
            for (int j = 0; j < 2; j++)
                wmma::load_matrix_sync(bb[j], sF + (k0 + ks * 8) * HLD + j * 16, HLD);
            #pragma unroll
            for (int i = 0; i < 4; i++)
                #pragma unroll
                for (int j = 0; j < 2; j++)
                    wmma::mma_sync(a1[i][j], a[i], bb[j], a1[i][j]);
        }
    }
    #pragma unroll
    for (int i = 0; i < 4; i++)
        #pragma unroll
        for (int j = 0; j < 2; j++)
            wmma::store_matrix_sync(sH + (wid * 64 + i * 16) * HLD + j * 16, a1[i][j], HLD, wmma::mem_row_major);
    __syncthreads();

    // bias + relu + tf32 in place
    #pragma unroll
    for (int j = 0; j < 64; j++) {
        int idx = j * 256 + tid;
        int r = idx >> 5, c = idx & 31;
        sH[r * HLD + c] = wmma::__float_to_tf32(fmaxf(sH[r * HLD + c] + b1[r], 0.f));
    }
    __syncthreads();

    // ---- GEMM out: [256 x 512] @ [512 x 32]; warp wid owns rows wid*32..+31 ----
    FragC a2[2][2];
    #pragma unroll
    for (int i = 0; i < 2; i++)
        #pragma unroll
        for (int j = 0; j < 2; j++) wmma::fill_fragment(a2[i][j], 0.f);

    for (int k0 = 0; k0 < 512; k0 += 16) {
        __syncthreads();
        #pragma unroll
        for (int j = 0; j < 16; j++) {
            int idx = j * 256 + tid;
            int kc = idx >> 8, r = idx & 255;
            sW[kc * W2LD + r] = g_W2P[(size_t)(k0 + kc) * 256 + r];
        }
        __syncthreads();
        #pragma unroll
        for (int ks = 0; ks < 2; ks++) {
            FragA a[2]; FragB bb[2];
            #pragma unroll
            for (int i = 0; i < 2; i++)
                wmma::load_matrix_sync(a[i], sW + ks * 8 * W2LD + wid * 32 + i * 16, W2LD);
            #pragma unroll
            for (int j = 0; j < 2; j++)
                wmma::load_matrix_sync(bb[j], sH + (k0 + ks * 8) * HLD + j * 16, HLD);
            #pragma unroll
            for (int i = 0; i < 2; i++)
                #pragma unroll
                for (int j = 0; j < 2; j++)
                    wmma::mma_sync(a2[i][j], a[i], bb[j], a2[i][j]);
        }
    }
    __syncthreads();   // sW still read as A by slower warps; sync before reuse as sO
    #pragma unroll
    for (int i = 0; i < 2; i++)
        #pragma unroll
        for (int j = 0; j < 2; j++)
            wmma::store_matrix_sync(sW + (wid * 32 + i * 16) * 32 + j * 16, a2[i][j], 32, wmma::mem_row_major);
    __syncthreads();

    // transpose out: out[(b*TGT + t)*256 + o]
    #pragma unroll
    for (int j = 0; j < 32; j++) {
        int idx = j * 256 + tid;
        int o = idx & 255, c = idx >> 8;
        int t = t0 + c;
        if (t < TGT)
            out[((size_t)b * TGT + t) * 256 + o] = sW[o * 32 + c] + b2[o];
    }
}

// ---------------- launch ----------------
static const int DIL[NL] = {1, 2, 4, 8, 16, 32, 64, 128, 256, 512,
                            1, 2, 4, 8, 16, 32, 64, 128, 256, 512};

extern "C" void kernel_launch(void* const* d_in, const int* in_sizes, int n_in,
                              void* d_out, int out_size) {
    const float* inputs = (const float*)d_in[0];
    const float* Wi = (const float*)d_in[1];
    const float* bi = (const float*)d_in[2];
    const float* Wf = (const float*)d_in[3];
    const float* bf = (const float*)d_in[4];
    const float* Wg = (const float*)d_in[5];
    const float* bg = (const float*)d_in[6];
    const float* Wr = (const float*)d_in[7];
    const float* br = (const float*)d_in[8];
    const float* W1 = (const float*)d_in[9];
    const float* b1 = (const float*)d_in[10];
    const float* W2 = (const float*)d_in[11];
    const float* b2 = (const float*)d_in[12];
    float* out = (float*)d_out;

    float *p_res0, *p_res1, *p_wip, *p_w1p, *p_w2p;
    cudaGetSymbolAddress((void**)&p_res0, g_res0);
    cudaGetSymbolAddress((void**)&p_res1, g_res1);
    cudaGetSymbolAddress((void**)&p_wip, g_WiP);
    cudaGetSymbolAddress((void**)&p_w1p, g_W1P);
    cudaGetSymbolAddress((void**)&p_w2p, g_W2P);

    const int SMEM_IC = (256 * XLD + 16 * WLDI) * 4;                 // 78336
    const int SMEM_LY = (256 * XLD + 16 * WLD1) * 4;                 // 86528
    const int SMEM_HD = (128 * HLD + 512 * HLD + 256 * 36) * 4;      // 129024

    cudaFuncSetAttribute(input_conv_k, cudaFuncAttributeMaxDynamicSharedMemorySize, SMEM_IC);
    cudaFuncSetAttribute(layer_k,      cudaFuncAttributeMaxDynamicSharedMemorySize, SMEM_LY);
    cudaFuncSetAttribute(head_k,       cudaFuncAttributeMaxDynamicSharedMemorySize, SMEM_HD);

    pack_fg<<<NL * 256 * 256 / 256, 256>>>(Wf, Wg);
    pack_r<<<NL * 128 * 128 / 256, 256>>>(Wr);
    pack_t<<<(INCH * HIDC) / 256, 256>>>(p_wip, Wi, HIDC, INCH);
    pack_t<<<(HIDC * MIDC) / 256, 256>>>(p_w1p, W1, MIDC, HIDC);
    pack_t<<<(MIDC * OUTC) / 256, 256>>>(p_w2p, W2, OUTC, MIDC);

    input_conv_k<<<dim3(T0C / 64, NBATCH), 256, SMEM_IC>>>(inputs, bi);

    int Tin = T0C;
    float* rin = p_res0;
    float* rout = p_res1;
    for (int l = 0; l < NL; l++) {
        int d = DIL[l];
        int Tout = Tin - d;
        dim3 grid((Tout + 63) / 64, NBATCH);
        layer_k<<<grid, 256, SMEM_LY>>>(rin, rout, bf, bg, br, l, d, Tin, Tout, l == 0 ? 1 : 0);
        float* tmp = rin; rin = rout; rout = tmp;
        Tin = Tout;
    }

    head_k<<<dim3((TGT + 31) / 32, NBATCH), 256, SMEM_HD>>>(b1, b2, out);
}